// round 6
// baseline (speedup 1.0000x reference)
#include <cuda_runtime.h>

#define N_    2
#define CIN   32
#define T_    8
#define H_    56
#define W_    56
#define COUT  64
#define KVOL  27
#define SP    25088   // T*H*W
#define HW    3136    // H*W

typedef unsigned long long u64;

// Scratch (no allocations allowed in kernel_launch)
__device__ float g_xt[(size_t)N_ * SP * CIN];   // x -> [N, T*H*W, C]
__device__ float g_wtd[KVOL * CIN * 128];       // w -> [k][c][co*2 + dup]  (each weight twice)

__device__ __forceinline__ u64 ffma2(u64 a, u64 b, u64 c) {
    u64 d; asm("fma.rn.f32x2 %0, %1, %2, %3;" : "=l"(d) : "l"(a), "l"(b), "l"(c));
    return d;
}
__device__ __forceinline__ void unpack2(u64 v, float& lo, float& hi) {
    asm("mov.b64 {%0, %1}, %2;" : "=f"(lo), "=f"(hi) : "l"(v));
}

// ---------------------------------------------------------------------------
// Merged prep: blocks [0,1568) transpose x; blocks [1568,1784) duplicate-transpose w.
// ---------------------------------------------------------------------------
__global__ __launch_bounds__(256) void prep(const float* __restrict__ x,
                                            const float* __restrict__ w) {
    __shared__ float sm[32][33];
    int bx = blockIdx.x;
    if (bx < 1568) {
        int n  = bx >= 784 ? 1 : 0;
        int sb = bx - n * 784;
        int s0 = sb * 32;
        int tx = threadIdx.x & 31;
        int ty = threadIdx.x >> 5;
#pragma unroll
        for (int r = 0; r < 4; ++r) {
            int c = ty + r * 8;
            sm[c][tx] = x[((size_t)n * CIN + c) * SP + s0 + tx];
        }
        __syncthreads();
#pragma unroll
        for (int r = 0; r < 4; ++r) {
            int j = ty + r * 8;
            g_xt[((size_t)n * SP + s0 + j) * CIN + tx] = sm[tx][j];
        }
    } else {
        int i = (bx - 1568) * 256 + threadIdx.x;   // 0 .. 55295 = 27*2048
        int k  = i >> 11;
        int r  = i & 2047;
        int c  = r >> 6;
        int co = r & 63;
        float v = w[((size_t)co * CIN + c) * KVOL + k];
        float* p = g_wtd + k * 4096 + c * 128 + co * 2;
        p[0] = v;
        p[1] = v;
    }
}

// ---------------------------------------------------------------------------
// Gather one tap into a col buffer. Warp-uniform branch, lane = channel.
// col layout: [pair = q>>1][c*2 + (q&1)]  (positions packed into u64 per c)
// ---------------------------------------------------------------------------
__device__ __forceinline__ void gather_tap(
    int k, const float* __restrict__ xb, const float* __restrict__ offp,
    const float* btc, const float* bhc, const float* bwc,
    int lane, int warpId, float* __restrict__ col)
{
    int kt = k / 9;
    int r9 = k - kt * 9;
    int kh = r9 / 3;
    int kw = r9 - kh * 3;
    float ktf = (float)kt, khf = (float)kh, kwf = (float)kw;

#pragma unroll
    for (int pp = 0; pp < 8; ++pp) {
        int q = warpId * 8 + pp;
        float pt = btc[pp] + ktf + offp[pp];                 // broadcast LDGs
        float ph = bhc[pp] + khf + offp[SP + pp];
        float pw = bwc[pp] + kwf + offp[2 * SP + pp];
        float tf = floorf(pt), hf = floorf(ph), wf = floorf(pw);
        int t0 = (int)tf, h0 = (int)hf, w0 = (int)wf;
        float lt = pt - tf, lh = ph - hf, lw = pw - wf;

        float val;
        if (t0 >= 0 && t0 <= T_ - 2 && h0 >= 0 && h0 <= H_ - 2 &&
            w0 >= 0 && w0 <= W_ - 2) {
            const float* p = xb + ((size_t)((t0 * H_ + h0) * W_ + w0) << 5) + lane;
            float v000 = p[0],        v001 = p[32];
            float v010 = p[W_ * 32],  v011 = p[W_ * 32 + 32];
            const float* p1 = p + HW * 32;
            float v100 = p1[0],       v101 = p1[32];
            float v110 = p1[W_ * 32], v111 = p1[W_ * 32 + 32];
            float c00 = v000 + lw * (v001 - v000);
            float c01 = v010 + lw * (v011 - v010);
            float c10 = v100 + lw * (v101 - v100);
            float c11 = v110 + lw * (v111 - v110);
            float c0 = c00 + lh * (c01 - c00);
            float c1 = c10 + lh * (c11 - c10);
            val = c0 + lt * (c1 - c0);
        } else {
            val = 0.f;
#pragma unroll
            for (int ct = 0; ct < 2; ++ct) {
                int ti = t0 + ct;
                float wt = ct ? lt : 1.f - lt;
                if (ti < 0 || ti >= T_) continue;
#pragma unroll
                for (int ch = 0; ch < 2; ++ch) {
                    int hi = h0 + ch;
                    float wh = ch ? lh : 1.f - lh;
                    if (hi < 0 || hi >= H_) continue;
#pragma unroll
                    for (int cw = 0; cw < 2; ++cw) {
                        int wi = w0 + cw;
                        float ww = cw ? lw : 1.f - lw;
                        if (wi < 0 || wi >= W_) continue;
                        val += wt * wh * ww *
                               xb[((size_t)((ti * H_ + hi) * W_ + wi) << 5) + lane];
                    }
                }
            }
        }
        col[(q >> 1) * 64 + (lane << 1) + (q & 1)] = val;
    }
}

// ---------------------------------------------------------------------------
// Main kernel: block = 64 positions x 64 couts, 256 threads.
// 2-buffer pipeline, ONE barrier per tap: [stage/gather k+1 ; FMA k ; bar].
// ---------------------------------------------------------------------------
__global__ __launch_bounds__(256) void deform_conv3d_main(
    const float* __restrict__ offset,
    const float* __restrict__ bias,
    float* __restrict__ out)
{
    __shared__ __align__(16) float colb[2][2048];   // 16 KB
    __shared__ __align__(16) float wbd[2][4096];    // 32 KB (duplicated weights)

    const int n   = blockIdx.y;
    const int s0  = blockIdx.x * 64;
    const int tid = threadIdx.x;
    const int lane   = tid & 31;     // phase 1: channel
    const int warpId = tid >> 5;     // 0..7
    const int cg = tid & 15;         // phase 2: cout quad (co = 4cg..4cg+3)
    const int pg = tid >> 4;         // phase 2: pos quad  (pos = 4pg..4pg+3)

    // base coords for this warp's 8 positions (registers, as in R2)
    float btc[8], bhc[8], bwc[8];
#pragma unroll
    for (int pp = 0; pp < 8; ++pp) {
        int s  = s0 + warpId * 8 + pp;
        int to = s / HW;
        int rem = s - to * HW;
        int ho = rem / W_;
        int wo = rem - ho * W_;
        btc[pp] = (float)(to - 1);
        bhc[pp] = (float)(ho - 1);
        bwc[pp] = (float)(wo - 1);
    }

    u64 acc[4][2];   // [cout in quad][pos u64 pair]; u64 = (pos even, pos odd)
#pragma unroll
    for (int i = 0; i < 4; ++i) { acc[i][0] = 0ull; acc[i][1] = 0ull; }

    const float* __restrict__ xb = g_xt + (size_t)n * SP * CIN;
    const float* __restrict__ offbase = offset + (size_t)n * 81 * SP + s0 + warpId * 8;

    // ---- prologue: stage + gather tap 0 ----
    {
        const float4* wg = (const float4*)(g_wtd);
        float4* ws = (float4*)wbd[0];
        ws[tid] = wg[tid]; ws[tid + 256] = wg[tid + 256];
        ws[tid + 512] = wg[tid + 512]; ws[tid + 768] = wg[tid + 768];
        gather_tap(0, xb, offbase, btc, bhc, bwc, lane, warpId, colb[0]);
    }
    __syncthreads();

#pragma unroll 1
    for (int k = 0; k < KVOL; ++k) {
        const int cur = k & 1;
        const int nxt = cur ^ 1;

        if (k + 1 < KVOL) {
            const float4* wg = (const float4*)(g_wtd + (k + 1) * 4096);
            float4* ws = (float4*)wbd[nxt];
            ws[tid] = wg[tid]; ws[tid + 256] = wg[tid + 256];
            ws[tid + 512] = wg[tid + 512]; ws[tid + 768] = wg[tid + 768];
            gather_tap(k + 1, xb, offbase + (size_t)(k + 1) * 3 * SP,
                       btc, bhc, bwc, lane, warpId, colb[nxt]);
        }

        // ---- FMA tap k: 4 couts x 4 pos, 12 issues per 8 FFMA2 ----
        {
            const float* cb = colb[cur];
            const float* wp = wbd[cur];
            const float* crow0 = cb + (pg << 7);   // pair 2pg
            const float* crow1 = crow0 + 64;       // pair 2pg+1
#pragma unroll
            for (int c = 0; c < 32; ++c) {
                const float* wr = wp + c * 128 + (cg << 3);
                ulonglong2 wA = *(const ulonglong2*)wr;        // couts 4cg,4cg+1 (dup)
                ulonglong2 wB = *(const ulonglong2*)(wr + 4);  // couts 4cg+2,4cg+3 (dup)
                u64 v0 = *(const u64*)(crow0 + (c << 1));      // pos 4pg,4pg+1
                u64 v1 = *(const u64*)(crow1 + (c << 1));      // pos 4pg+2,4pg+3
                acc[0][0] = ffma2(wA.x, v0, acc[0][0]);
                acc[0][1] = ffma2(wA.x, v1, acc[0][1]);
                acc[1][0] = ffma2(wA.y, v0, acc[1][0]);
                acc[1][1] = ffma2(wA.y, v1, acc[1][1]);
                acc[2][0] = ffma2(wB.x, v0, acc[2][0]);
                acc[2][1] = ffma2(wB.x, v1, acc[2][1]);
                acc[3][0] = ffma2(wB.y, v0, acc[3][0]);
                acc[3][1] = ffma2(wB.y, v1, acc[3][1]);
            }
        }
        __syncthreads();
    }

    // ---- epilogue: unpack, add bias, float4 stores (R2 shape) ----
    float4 b4 = *(const float4*)(bias + (cg << 2));
    float bb[4] = {b4.x, b4.y, b4.z, b4.w};
#pragma unroll
    for (int i = 0; i < 4; ++i) {
        float x0, x1, x2, x3;
        unpack2(acc[i][0], x0, x1);
        unpack2(acc[i][1], x2, x3);
        float4 o;
        o.x = x0 + bb[i]; o.y = x1 + bb[i]; o.z = x2 + bb[i]; o.w = x3 + bb[i];
        *(float4*)(out + ((size_t)n * COUT + (cg << 2) + i) * SP + s0 + (pg << 2)) = o;
    }
}

// ---------------------------------------------------------------------------
extern "C" void kernel_launch(void* const* d_in, const int* in_sizes, int n_in,
                              void* d_out, int out_size) {
    const float* x      = (const float*)d_in[0];
    const float* offset = (const float*)d_in[1];
    const float* weight = (const float*)d_in[2];
    const float* bias   = (const float*)d_in[3];
    float* out = (float*)d_out;

    prep<<<1784, 256>>>(x, weight);

    dim3 gM(SP / 64, N_);
    deform_conv3d_main<<<gM, 256>>>(offset, bias, out);
}

// round 7
// speedup vs baseline: 2.2238x; 2.2238x over previous
#include <cuda_runtime.h>
#include <cstdint>

#define N_    2
#define CIN   32
#define T_    8
#define H_    56
#define W_    56
#define COUT  64
#define KVOL  27
#define SP    25088   // T*H*W
#define HW    3136    // H*W
#define WROW  72      // wsm row stride: [c][co], padded 64->72 (A-frag conflict-free)
#define CROW  36      // col row stride: [pos][c], padded 32->36 (B-frag conflict-free)
#define WTAP  (CIN * WROW)   // 2304 floats per tap

// Scratch (no allocations allowed in kernel_launch)
__device__ float g_xt[(size_t)N_ * SP * CIN];   // x -> [N, T*H*W, C]
__device__ float g_wt[KVOL * WTAP];             // w -> [k][c(pad WROW)][co], tf32-rounded

__device__ __forceinline__ uint32_t f2tf32(float f) {
    uint32_t r; asm("cvt.rna.tf32.f32 %0, %1;" : "=r"(r) : "f"(f));
    return r;
}

// ---------------------------------------------------------------------------
// Merged prep: blocks [0,1568) transpose x; blocks [1568,1784) prep weights.
// ---------------------------------------------------------------------------
__global__ __launch_bounds__(256) void prep(const float* __restrict__ x,
                                            const float* __restrict__ w) {
    __shared__ float sm[32][33];
    int bx = blockIdx.x;
    if (bx < 1568) {
        int n  = bx >= 784 ? 1 : 0;
        int sb = bx - n * 784;
        int s0 = sb * 32;
        int tx = threadIdx.x & 31;
        int ty = threadIdx.x >> 5;
#pragma unroll
        for (int r = 0; r < 4; ++r) {
            int c = ty + r * 8;
            sm[c][tx] = x[((size_t)n * CIN + c) * SP + s0 + tx];
        }
        __syncthreads();
#pragma unroll
        for (int r = 0; r < 4; ++r) {
            int j = ty + r * 8;
            g_xt[((size_t)n * SP + s0 + j) * CIN + tx] = sm[tx][j];
        }
    } else {
        int i = (bx - 1568) * 256 + threadIdx.x;   // 0 .. 55295 = 27*2048
        int k  = i >> 11;
        int r  = i & 2047;
        int c  = r >> 6;
        int co = r & 63;
        float v = w[((size_t)co * CIN + c) * KVOL + k];
        g_wt[k * WTAP + c * WROW + co] = __uint_as_float(f2tf32(v));
    }
}

// ---------------------------------------------------------------------------
// Main kernel: block = 64 positions x 64 couts, 256 threads.
// Phase 1 = R2's proven gather (lane = channel, warp-uniform branch, osm).
// Phase 2 = tf32 mma.sync m16n8k8: warp = (co 16-band, pos 32-half).
// ---------------------------------------------------------------------------
__global__ __launch_bounds__(256) void deform_conv3d_main(
    const float* __restrict__ offset,
    const float* __restrict__ bias,
    float* __restrict__ out)
{
    __shared__ __align__(16) float col[64 * CROW];   // [pos][c] 9.2 KB
    __shared__ __align__(16) float wsm[WTAP];        // [c][co]  9.2 KB
    __shared__ float osm[81 * 64];                   // offsets  20.7 KB

    const int n   = blockIdx.y;
    const int s0  = blockIdx.x * 64;
    const int tid = threadIdx.x;
    const int lane   = tid & 31;     // phase 1: channel
    const int warpId = tid >> 5;     // 0..7

    // phase-2 fragment coordinates
    const int g  = lane >> 2;        // 0..7
    const int tg = lane & 3;         // 0..3
    const int cobase = (warpId & 3) * 16;
    const int pbase  = (warpId >> 2) * 32;

    // stage offsets for the block (coalesced, once)
    for (int i = tid; i < 81 * 64; i += 256) {
        int ch = i >> 6, j = i & 63;
        osm[i] = offset[((size_t)n * 81 + ch) * SP + s0 + j];
    }

    // base coords for this warp's 8 positions
    float btc[8], bhc[8], bwc[8];
#pragma unroll
    for (int pp = 0; pp < 8; ++pp) {
        int s  = s0 + warpId * 8 + pp;
        int to = s / HW;
        int rem = s - to * HW;
        int ho = rem / W_;
        int wo = rem - ho * W_;
        btc[pp] = (float)(to - 1);
        bhc[pp] = (float)(ho - 1);
        bwc[pp] = (float)(wo - 1);
    }

    float d[4][4];   // [ntile][reg] accumulators
#pragma unroll
    for (int j = 0; j < 4; ++j)
#pragma unroll
        for (int i = 0; i < 4; ++i) d[j][i] = 0.f;

    const float* __restrict__ xb = g_xt + (size_t)n * SP * CIN;
    __syncthreads();   // osm ready

    for (int k = 0; k < KVOL; ++k) {
        __syncthreads();   // protect col/wsm consumed in previous iteration

        // ---- stage weight slice (tf32 bits, final layout) ----
        {
            const float4* wg = (const float4*)(g_wt + k * WTAP);
            float4* ws = (float4*)wsm;
            ws[tid]       = wg[tid];
            ws[tid + 256] = wg[tid + 256];
            if (tid < 64) ws[tid + 512] = wg[tid + 512];
        }

        int kt = k / 9;
        int r9 = k - kt * 9;
        int kh = r9 / 3;
        int kw = r9 - kh * 3;
        float ktf = (float)kt, khf = (float)kh, kwf = (float)kw;
        const float* o0 = osm + (k * 3 + 0) * 64;
        const float* o1 = osm + (k * 3 + 1) * 64;
        const float* o2 = osm + (k * 3 + 2) * 64;

        // ---- phase 1: trilinear gather (R2 shape), tf32-rounded store ----
#pragma unroll
        for (int pp = 0; pp < 8; ++pp) {
            int q = warpId * 8 + pp;
            float pt = btc[pp] + ktf + o0[q];
            float ph = bhc[pp] + khf + o1[q];
            float pw = bwc[pp] + kwf + o2[q];
            float tf = floorf(pt), hf = floorf(ph), wf = floorf(pw);
            int t0 = (int)tf, h0 = (int)hf, w0 = (int)wf;
            float lt = pt - tf, lh = ph - hf, lw = pw - wf;

            float val;
            if (t0 >= 0 && t0 <= T_ - 2 && h0 >= 0 && h0 <= H_ - 2 &&
                w0 >= 0 && w0 <= W_ - 2) {
                const float* p = xb + ((size_t)((t0 * H_ + h0) * W_ + w0) << 5) + lane;
                float v000 = p[0],        v001 = p[32];
                float v010 = p[W_ * 32],  v011 = p[W_ * 32 + 32];
                const float* p1 = p + HW * 32;
                float v100 = p1[0],       v101 = p1[32];
                float v110 = p1[W_ * 32], v111 = p1[W_ * 32 + 32];
                float c00 = v000 + lw * (v001 - v000);
                float c01 = v010 + lw * (v011 - v010);
                float c10 = v100 + lw * (v101 - v100);
                float c11 = v110 + lw * (v111 - v110);
                float c0 = c00 + lh * (c01 - c00);
                float c1 = c10 + lh * (c11 - c10);
                val = c0 + lt * (c1 - c0);
            } else {
                val = 0.f;
#pragma unroll
                for (int ct = 0; ct < 2; ++ct) {
                    int ti = t0 + ct;
                    float wt = ct ? lt : 1.f - lt;
                    if (ti < 0 || ti >= T_) continue;
#pragma unroll
                    for (int ch = 0; ch < 2; ++ch) {
                        int hi = h0 + ch;
                        float wh = ch ? lh : 1.f - lh;
                        if (hi < 0 || hi >= H_) continue;
#pragma unroll
                        for (int cw = 0; cw < 2; ++cw) {
                            int wi = w0 + cw;
                            float ww = cw ? lw : 1.f - lw;
                            if (wi < 0 || wi >= W_) continue;
                            val += wt * wh * ww *
                                   xb[((size_t)((ti * H_ + hi) * W_ + wi) << 5) + lane];
                        }
                    }
                }
            }
            col[q * CROW + lane] = __uint_as_float(f2tf32(val));
        }
        __syncthreads();

        // ---- phase 2: 16 x mma.m16n8k8.tf32 per warp ----
#pragma unroll
        for (int kk = 0; kk < 4; ++kk) {
            const int cb = kk * 8;
            const float* wr  = wsm + (cb + tg) * WROW + cobase;
            const float* wr2 = wr + 4 * WROW;
            uint32_t a0 = *(const uint32_t*)(wr  + g);
            uint32_t a1 = *(const uint32_t*)(wr  + g + 8);
            uint32_t a2 = *(const uint32_t*)(wr2 + g);
            uint32_t a3 = *(const uint32_t*)(wr2 + g + 8);
#pragma unroll
            for (int j = 0; j < 4; ++j) {
                const float* cr = col + (pbase + 8 * j + g) * CROW + cb + tg;
                uint32_t b0 = *(const uint32_t*)(cr);
                uint32_t b1 = *(const uint32_t*)(cr + 4);
                asm("mma.sync.aligned.m16n8k8.row.col.f32.tf32.tf32.f32 "
                    "{%0,%1,%2,%3}, {%4,%5,%6,%7}, {%8,%9}, {%0,%1,%2,%3};"
                    : "+f"(d[j][0]), "+f"(d[j][1]), "+f"(d[j][2]), "+f"(d[j][3])
                    : "r"(a0), "r"(a1), "r"(a2), "r"(a3), "r"(b0), "r"(b1));
            }
        }
    }

    // ---- epilogue: add bias, float2 stores ----
    float bg  = bias[cobase + g];
    float bg8 = bias[cobase + g + 8];
    float* ob0 = out + ((size_t)n * COUT + cobase + g)     * SP + s0 + pbase + 2 * tg;
    float* ob1 = out + ((size_t)n * COUT + cobase + g + 8) * SP + s0 + pbase + 2 * tg;
#pragma unroll
    for (int j = 0; j < 4; ++j) {
        *(float2*)(ob0 + 8 * j) = make_float2(d[j][0] + bg,  d[j][1] + bg);
        *(float2*)(ob1 + 8 * j) = make_float2(d[j][2] + bg8, d[j][3] + bg8);
    }
}

// ---------------------------------------------------------------------------
extern "C" void kernel_launch(void* const* d_in, const int* in_sizes, int n_in,
                              void* d_out, int out_size) {
    const float* x      = (const float*)d_in[0];
    const float* offset = (const float*)d_in[1];
    const float* weight = (const float*)d_in[2];
    const float* bias   = (const float*)d_in[3];
    float* out = (float*)d_out;

    prep<<<1784, 256>>>(x, weight);

    dim3 gM(SP / 64, N_);
    deform_conv3d_main<<<gM, 256>>>(offset, bias, out);
}

// round 8
// speedup vs baseline: 2.2641x; 1.0181x over previous
#include <cuda_runtime.h>
#include <cstdint>

#define N_    2
#define CIN   32
#define T_    8
#define H_    56
#define W_    56
#define COUT  64
#define KVOL  27
#define SP    25088   // T*H*W
#define HW    3136    // H*W
#define WROW  72      // wsm row stride: [c][co], padded 64->72 (A-frag conflict-free)
#define CROW  36      // col row stride: [pos][c], padded 32->36 (B-frag conflict-free)
#define WTAP  (CIN * WROW)   // 2304 floats per tap

// Scratch (no allocations allowed in kernel_launch)
__device__ float g_xt[(size_t)N_ * SP * CIN];   // x -> [N, T*H*W, C]
__device__ float g_wt[KVOL * WTAP];             // w -> [k][c(pad WROW)][co], tf32-rounded

__device__ __forceinline__ uint32_t f2tf32(float f) {
    uint32_t r; asm("cvt.rna.tf32.f32 %0, %1;" : "=r"(r) : "f"(f));
    return r;
}

// ---------------------------------------------------------------------------
// Merged prep: blocks [0,1568) transpose x; blocks [1568,1784) prep weights.
// ---------------------------------------------------------------------------
__global__ __launch_bounds__(256) void prep(const float* __restrict__ x,
                                            const float* __restrict__ w) {
    __shared__ float sm[32][33];
    int bx = blockIdx.x;
    if (bx < 1568) {
        int n  = bx >= 784 ? 1 : 0;
        int sb = bx - n * 784;
        int s0 = sb * 32;
        int tx = threadIdx.x & 31;
        int ty = threadIdx.x >> 5;
#pragma unroll
        for (int r = 0; r < 4; ++r) {
            int c = ty + r * 8;
            sm[c][tx] = x[((size_t)n * CIN + c) * SP + s0 + tx];
        }
        __syncthreads();
#pragma unroll
        for (int r = 0; r < 4; ++r) {
            int j = ty + r * 8;
            g_xt[((size_t)n * SP + s0 + j) * CIN + tx] = sm[tx][j];
        }
    } else {
        int i = (bx - 1568) * 256 + threadIdx.x;   // 0 .. 55295 = 27*2048
        int k  = i >> 11;
        int r  = i & 2047;
        int c  = r >> 6;
        int co = r & 63;
        float v = w[((size_t)co * CIN + c) * KVOL + k];
        g_wt[k * WTAP + c * WROW + co] = __uint_as_float(f2tf32(v));
    }
}

// ---------------------------------------------------------------------------
// Gather one tap into col buffer + stage its weight slice.
// Warp-uniform branch, lane = channel (R7 shape).
// ---------------------------------------------------------------------------
__device__ __forceinline__ void gather_and_stage(
    int k, const float* __restrict__ xb, const float* __restrict__ osm,
    const float* btc, const float* bhc, const float* bwc,
    int lane, int warpId, int tid,
    float* __restrict__ col, float* __restrict__ wsm)
{
    // stage weight slice (tf32 bits, final layout)
    {
        const float4* wg = (const float4*)(g_wt + k * WTAP);
        float4* ws = (float4*)wsm;
        ws[tid]       = wg[tid];
        ws[tid + 256] = wg[tid + 256];
        if (tid < 64) ws[tid + 512] = wg[tid + 512];
    }

    int kt = k / 9;
    int r9 = k - kt * 9;
    int kh = r9 / 3;
    int kw = r9 - kh * 3;
    float ktf = (float)kt, khf = (float)kh, kwf = (float)kw;
    const float* o0 = osm + (k * 3 + 0) * 64;
    const float* o1 = osm + (k * 3 + 1) * 64;
    const float* o2 = osm + (k * 3 + 2) * 64;

#pragma unroll
    for (int pp = 0; pp < 8; ++pp) {
        int q = warpId * 8 + pp;
        float pt = btc[pp] + ktf + o0[q];
        float ph = bhc[pp] + khf + o1[q];
        float pw = bwc[pp] + kwf + o2[q];
        float tf = floorf(pt), hf = floorf(ph), wf = floorf(pw);
        int t0 = (int)tf, h0 = (int)hf, w0 = (int)wf;
        float lt = pt - tf, lh = ph - hf, lw = pw - wf;

        float val;
        if (t0 >= 0 && t0 <= T_ - 2 && h0 >= 0 && h0 <= H_ - 2 &&
            w0 >= 0 && w0 <= W_ - 2) {
            const float* p = xb + ((size_t)((t0 * H_ + h0) * W_ + w0) << 5) + lane;
            float v000 = p[0],        v001 = p[32];
            float v010 = p[W_ * 32],  v011 = p[W_ * 32 + 32];
            const float* p1 = p + HW * 32;
            float v100 = p1[0],       v101 = p1[32];
            float v110 = p1[W_ * 32], v111 = p1[W_ * 32 + 32];
            float c00 = v000 + lw * (v001 - v000);
            float c01 = v010 + lw * (v011 - v010);
            float c10 = v100 + lw * (v101 - v100);
            float c11 = v110 + lw * (v111 - v110);
            float c0 = c00 + lh * (c01 - c00);
            float c1 = c10 + lh * (c11 - c10);
            val = c0 + lt * (c1 - c0);
        } else {
            val = 0.f;
#pragma unroll
            for (int ct = 0; ct < 2; ++ct) {
                int ti = t0 + ct;
                float wt = ct ? lt : 1.f - lt;
                if (ti < 0 || ti >= T_) continue;
#pragma unroll
                for (int ch = 0; ch < 2; ++ch) {
                    int hi = h0 + ch;
                    float wh = ch ? lh : 1.f - lh;
                    if (hi < 0 || hi >= H_) continue;
#pragma unroll
                    for (int cw = 0; cw < 2; ++cw) {
                        int wi = w0 + cw;
                        float ww = cw ? lw : 1.f - lw;
                        if (wi < 0 || wi >= W_) continue;
                        val += wt * wh * ww *
                               xb[((size_t)((ti * H_ + hi) * W_ + wi) << 5) + lane];
                    }
                }
            }
        }
        col[q * CROW + lane] = __uint_as_float(f2tf32(val));
    }
}

// ---------------------------------------------------------------------------
// Main kernel: block = 64 positions x 64 couts, 256 threads.
// Double-buffered col/wsm, ONE barrier per tap:
//   [stage+gather(k+1) -> buf nxt ; mma(k) on buf cur ; bar]
// ---------------------------------------------------------------------------
__global__ __launch_bounds__(256) void deform_conv3d_main(
    const float* __restrict__ offset,
    const float* __restrict__ bias,
    float* __restrict__ out)
{
    __shared__ __align__(16) float col[2][64 * CROW];   // 18.4 KB
    __shared__ __align__(16) float wsm[2][WTAP];        // 18.4 KB
    __shared__ float osm[81 * 64];                      // 20.7 KB

    const int n   = blockIdx.y;
    const int s0  = blockIdx.x * 64;
    const int tid = threadIdx.x;
    const int lane   = tid & 31;     // phase 1: channel
    const int warpId = tid >> 5;     // 0..7

    // phase-2 fragment coordinates
    const int g  = lane >> 2;        // 0..7
    const int tg = lane & 3;         // 0..3
    const int cobase = (warpId & 3) * 16;
    const int pbase  = (warpId >> 2) * 32;

    // stage offsets for the block (coalesced, once)
    for (int i = tid; i < 81 * 64; i += 256) {
        int ch = i >> 6, j = i & 63;
        osm[i] = offset[((size_t)n * 81 + ch) * SP + s0 + j];
    }

    // base coords for this warp's 8 positions
    float btc[8], bhc[8], bwc[8];
#pragma unroll
    for (int pp = 0; pp < 8; ++pp) {
        int s  = s0 + warpId * 8 + pp;
        int to = s / HW;
        int rem = s - to * HW;
        int ho = rem / W_;
        int wo = rem - ho * W_;
        btc[pp] = (float)(to - 1);
        bhc[pp] = (float)(ho - 1);
        bwc[pp] = (float)(wo - 1);
    }

    float d[4][4];
#pragma unroll
    for (int j = 0; j < 4; ++j)
#pragma unroll
        for (int i = 0; i < 4; ++i) d[j][i] = 0.f;

    const float* __restrict__ xb = g_xt + (size_t)n * SP * CIN;
    __syncthreads();   // osm ready

    // prologue: fill buffer 0 with tap 0
    gather_and_stage(0, xb, osm, btc, bhc, bwc, lane, warpId, tid,
                     col[0], wsm[0]);
    __syncthreads();

#pragma unroll 1
    for (int k = 0; k < KVOL; ++k) {
        const int cur = k & 1;
        const int nxt = cur ^ 1;

        if (k + 1 < KVOL)
            gather_and_stage(k + 1, xb, osm, btc, bhc, bwc, lane, warpId, tid,
                             col[nxt], wsm[nxt]);

        // ---- mma tap k: 16 x m16n8k8.tf32 per warp ----
        {
            const float* cb = col[cur];
            const float* wb = wsm[cur];
#pragma unroll
            for (int kk = 0; kk < 4; ++kk) {
                const int cbk = kk * 8;
                const float* wr  = wb + (cbk + tg) * WROW + cobase;
                const float* wr2 = wr + 4 * WROW;
                uint32_t a0 = *(const uint32_t*)(wr  + g);
                uint32_t a1 = *(const uint32_t*)(wr  + g + 8);
                uint32_t a2 = *(const uint32_t*)(wr2 + g);
                uint32_t a3 = *(const uint32_t*)(wr2 + g + 8);
#pragma unroll
                for (int j = 0; j < 4; ++j) {
                    const float* cr = cb + (pbase + 8 * j + g) * CROW + cbk + tg;
                    uint32_t b0 = *(const uint32_t*)(cr);
                    uint32_t b1 = *(const uint32_t*)(cr + 4);
                    asm("mma.sync.aligned.m16n8k8.row.col.f32.tf32.tf32.f32 "
                        "{%0,%1,%2,%3}, {%4,%5,%6,%7}, {%8,%9}, {%0,%1,%2,%3};"
                        : "+f"(d[j][0]), "+f"(d[j][1]), "+f"(d[j][2]), "+f"(d[j][3])
                        : "r"(a0), "r"(a1), "r"(a2), "r"(a3), "r"(b0), "r"(b1));
                }
            }
        }
        __syncthreads();
    }

    // ---- epilogue: add bias, float2 stores ----
    float bg  = bias[cobase + g];
    float bg8 = bias[cobase + g + 8];
    float* ob0 = out + ((size_t)n * COUT + cobase + g)     * SP + s0 + pbase + 2 * tg;
    float* ob1 = out + ((size_t)n * COUT + cobase + g + 8) * SP + s0 + pbase + 2 * tg;
#pragma unroll
    for (int j = 0; j < 4; ++j) {
        *(float2*)(ob0 + 8 * j) = make_float2(d[j][0] + bg,  d[j][1] + bg);
        *(float2*)(ob1 + 8 * j) = make_float2(d[j][2] + bg8, d[j][3] + bg8);
    }
}

// ---------------------------------------------------------------------------
extern "C" void kernel_launch(void* const* d_in, const int* in_sizes, int n_in,
                              void* d_out, int out_size) {
    const float* x      = (const float*)d_in[0];
    const float* offset = (const float*)d_in[1];
    const float* weight = (const float*)d_in[2];
    const float* bias   = (const float*)d_in[3];
    float* out = (float*)d_out;

    prep<<<1784, 256>>>(x, weight);

    dim3 gM(SP / 64, N_);
    deform_conv3d_main<<<gM, 256>>>(offset, bias, out);
}

// round 9
// speedup vs baseline: 2.3549x; 1.0401x over previous
#include <cuda_runtime.h>
#include <cstdint>

#define N_    2
#define CIN   32
#define T_    8
#define H_    56
#define W_    56
#define COUT  64
#define KVOL  27
#define SP    25088   // T*H*W
#define HW    3136    // H*W
#define CROW  36      // col row stride: [pos][c], padded 32->36 (B-frag conflict-free)

// Scratch (no allocations allowed in kernel_launch)
__device__ float    g_xt[(size_t)N_ * SP * CIN];   // x -> [N, T*H*W, C]
__device__ uint32_t g_wfrag[KVOL * 2048];          // w -> [k][fragword(16)][c4*32+lane], tf32

__device__ __forceinline__ uint32_t f2tf32(float f) {
    uint32_t r; asm("cvt.rna.tf32.f32 %0, %1;" : "=r"(r) : "f"(f));
    return r;
}

// ---------------------------------------------------------------------------
// Merged prep: blocks [0,1568) transpose x; blocks [1568,1784) build w frags.
// ---------------------------------------------------------------------------
__global__ __launch_bounds__(256) void prep(const float* __restrict__ x,
                                            const float* __restrict__ w) {
    __shared__ float sm[32][33];
    int bx = blockIdx.x;
    if (bx < 1568) {
        int n  = bx >= 784 ? 1 : 0;
        int sb = bx - n * 784;
        int s0 = sb * 32;
        int tx = threadIdx.x & 31;
        int ty = threadIdx.x >> 5;
#pragma unroll
        for (int r = 0; r < 4; ++r) {
            int c = ty + r * 8;
            sm[c][tx] = x[((size_t)n * CIN + c) * SP + s0 + tx];
        }
        __syncthreads();
#pragma unroll
        for (int r = 0; r < 4; ++r) {
            int j = ty + r * 8;
            g_xt[((size_t)n * SP + s0 + j) * CIN + tx] = sm[tx][j];
        }
    } else {
        // fragment-ordered weights for mma.m16n8k8 (A row-major = [co][c])
        int i = (bx - 1568) * 256 + threadIdx.x;   // 0 .. 55295 = 27*2048
        int k  = i >> 11;          // tap
        int r  = i & 2047;
        int wd = r >> 7;           // frag word 0..15 = kk*4 + rr
        int t  = r & 127;
        int c4 = t >> 5;           // cout band
        int ln = t & 31;
        int g  = ln >> 2, tg = ln & 3;
        int kk = wd >> 2, rr = wd & 3;
        int co = c4 * 16 + g + (rr & 1) * 8;
        int c  = kk * 8 + tg + (rr >> 1) * 4;
        g_wfrag[i] = f2tf32(w[((size_t)co * CIN + c) * KVOL + k]);
    }
}

// ---------------------------------------------------------------------------
// Branchless trilinear gather of one tap into a col buffer.
// lane = channel; per position: clamp + masked per-dim weights, 8 LDGs.
// ---------------------------------------------------------------------------
__device__ __forceinline__ void gather_tap(
    int k, const float* __restrict__ xb, const float* __restrict__ osm,
    int lane, int warpId, float* __restrict__ col)
{
    int kt = k / 9;
    int r9 = k - kt * 9;
    int kh = r9 / 3;
    int kw = r9 - kh * 3;
    float ktf = (float)kt, khf = (float)kh, kwf = (float)kw;
    const float* o0 = osm + (k * 3 + 0) * 64;   // offset + (to-1)
    const float* o1 = osm + (k * 3 + 1) * 64;   // offset + (ho-1)
    const float* o2 = osm + (k * 3 + 2) * 64;   // offset + (wo-1)

#pragma unroll
    for (int pp = 0; pp < 8; ++pp) {
        int q = warpId * 8 + pp;
        float pt = o0[q] + ktf;
        float ph = o1[q] + khf;
        float pw = o2[q] + kwf;
        float tf = floorf(pt), hf = floorf(ph), wf = floorf(pw);
        int t0 = (int)tf, h0 = (int)hf, w0 = (int)wf;
        float lt = pt - tf, lh = ph - hf, lw = pw - wf;

        // per-dim masked weights (zero if that slice is out of range)
        float wt0 = (t0 >= 0 && t0 < T_)         ? 1.f - lt : 0.f;
        float wt1 = (t0 + 1 >= 0 && t0 + 1 < T_) ? lt       : 0.f;
        float wh0 = (h0 >= 0 && h0 < H_)         ? 1.f - lh : 0.f;
        float wh1 = (h0 + 1 >= 0 && h0 + 1 < H_) ? lh       : 0.f;
        float ww0 = (w0 >= 0 && w0 < W_)         ? 1.f - lw : 0.f;
        float ww1 = (w0 + 1 >= 0 && w0 + 1 < W_) ? lw       : 0.f;

        // clamped coordinates
        int t0c = min(max(t0, 0), T_ - 1), t1c = min(max(t0 + 1, 0), T_ - 1);
        int h0c = min(max(h0, 0), H_ - 1), h1c = min(max(h0 + 1, 0), H_ - 1);
        int w0c = min(max(w0, 0), W_ - 1), w1c = min(max(w0 + 1, 0), W_ - 1);

        int i00 = (t0c * H_ + h0c) * W_;
        int i01 = (t0c * H_ + h1c) * W_;
        int i10 = (t1c * H_ + h0c) * W_;
        int i11 = (t1c * H_ + h1c) * W_;

        const float* b = xb + lane;
        float v000 = b[(size_t)(i00 + w0c) << 5];
        float v001 = b[(size_t)(i00 + w1c) << 5];
        float v010 = b[(size_t)(i01 + w0c) << 5];
        float v011 = b[(size_t)(i01 + w1c) << 5];
        float v100 = b[(size_t)(i10 + w0c) << 5];
        float v101 = b[(size_t)(i10 + w1c) << 5];
        float v110 = b[(size_t)(i11 + w0c) << 5];
        float v111 = b[(size_t)(i11 + w1c) << 5];

        float m00 = wt0 * wh0, m01 = wt0 * wh1;
        float m10 = wt1 * wh0, m11 = wt1 * wh1;
        float val;
        val  = v000 * (m00 * ww0);
        val += v001 * (m00 * ww1);
        val += v010 * (m01 * ww0);
        val += v011 * (m01 * ww1);
        val += v100 * (m10 * ww0);
        val += v101 * (m10 * ww1);
        val += v110 * (m11 * ww0);
        val += v111 * (m11 * ww1);

        col[q * CROW + lane] = __uint_as_float(f2tf32(val));
    }
}

// ---------------------------------------------------------------------------
// Main kernel: block = 64 positions x 64 couts, 256 threads, 4 blocks/SM.
// Double-buffered col, ONE barrier per tap; A-frags straight from global.
// ---------------------------------------------------------------------------
__global__ __launch_bounds__(256, 4) void deform_conv3d_main(
    const float* __restrict__ offset,
    const float* __restrict__ bias,
    float* __restrict__ out)
{
    __shared__ __align__(16) float col[2][64 * CROW];   // 18.4 KB
    __shared__ float osm[81 * 64];                      // 20.7 KB (offset + base)

    const int n   = blockIdx.y;
    const int s0  = blockIdx.x * 64;
    const int tid = threadIdx.x;
    const int lane   = tid & 31;
    const int warpId = tid >> 5;

    const int g  = lane >> 2;
    const int tg = lane & 3;
    const int cobase = (warpId & 3) * 16;
    const int pbase  = (warpId >> 2) * 32;

    // stage offsets + base coordinates (coalesced read, once)
    for (int i = tid; i < 81 * 64; i += 256) {
        int ch = i >> 6, j = i & 63;
        int dim = ch - (ch / 3) * 3;
        int s = s0 + j;
        int base;
        if (dim == 0)      base = s / HW - 1;
        else if (dim == 1) base = (s % HW) / W_ - 1;
        else               base = s % W_ - 1;
        osm[i] = offset[((size_t)n * 81 + ch) * SP + s] + (float)base;
    }

    float d[4][4];
#pragma unroll
    for (int j = 0; j < 4; ++j)
#pragma unroll
        for (int i = 0; i < 4; ++i) d[j][i] = 0.f;

    const float* __restrict__ xb = g_xt + (size_t)n * SP * CIN;
    const uint32_t* __restrict__ wfrag =
        g_wfrag + (warpId & 3) * 32 + lane;

    __syncthreads();   // osm ready

    gather_tap(0, xb, osm, lane, warpId, col[0]);
    __syncthreads();

#pragma unroll 1
    for (int k = 0; k < KVOL; ++k) {
        const int cur = k & 1;
        const int nxt = cur ^ 1;

        if (k + 1 < KVOL)
            gather_tap(k + 1, xb, osm, lane, warpId, col[nxt]);

        // ---- mma tap k: A-frags from global (coalesced, L1/L2-hot) ----
        {
            const float* cb = col[cur];
            const uint32_t* wf = wfrag + k * 2048;
#pragma unroll
            for (int kk = 0; kk < 4; ++kk) {
                uint32_t a0 = wf[(kk * 4 + 0) * 128];
                uint32_t a1 = wf[(kk * 4 + 1) * 128];
                uint32_t a2 = wf[(kk * 4 + 2) * 128];
                uint32_t a3 = wf[(kk * 4 + 3) * 128];
                const int cbk = kk * 8;
#pragma unroll
                for (int j = 0; j < 4; ++j) {
                    const float* cr = cb + (pbase + 8 * j + g) * CROW + cbk + tg;
                    uint32_t b0 = *(const uint32_t*)(cr);
                    uint32_t b1 = *(const uint32_t*)(cr + 4);
                    asm("mma.sync.aligned.m16n8k8.row.col.f32.tf32.tf32.f32 "
                        "{%0,%1,%2,%3}, {%4,%5,%6,%7}, {%8,%9}, {%0,%1,%2,%3};"
                        : "+f"(d[j][0]), "+f"(d[j][1]), "+f"(d[j][2]), "+f"(d[j][3])
                        : "r"(a0), "r"(a1), "r"(a2), "r"(a3), "r"(b0), "r"(b1));
                }
            }
        }
        __syncthreads();
    }

    // ---- epilogue: add bias, float2 stores ----
    float bg  = bias[cobase + g];
    float bg8 = bias[cobase + g + 8];
    float* ob0 = out + ((size_t)n * COUT + cobase + g)     * SP + s0 + pbase + 2 * tg;
    float* ob1 = out + ((size_t)n * COUT + cobase + g + 8) * SP + s0 + pbase + 2 * tg;
#pragma unroll
    for (int j = 0; j < 4; ++j) {
        *(float2*)(ob0 + 8 * j) = make_float2(d[j][0] + bg,  d[j][1] + bg);
        *(float2*)(ob1 + 8 * j) = make_float2(d[j][2] + bg8, d[j][3] + bg8);
    }
}

// ---------------------------------------------------------------------------
extern "C" void kernel_launch(void* const* d_in, const int* in_sizes, int n_in,
                              void* d_out, int out_size) {
    const float* x      = (const float*)d_in[0];
    const float* offset = (const float*)d_in[1];
    const float* weight = (const float*)d_in[2];
    const float* bias   = (const float*)d_in[3];
    float* out = (float*)d_out;

    prep<<<1784, 256>>>(x, weight);

    dim3 gM(SP / 64, N_);
    deform_conv3d_main<<<gM, 256>>>(offset, bias, out);
}